// round 2
// baseline (speedup 1.0000x reference)
#include <cuda_runtime.h>
#include <cuda_bf16.h>
#include <math_constants.h>

#define NN 100000
#define EE 1600000
#define F_IN 256
#define HH 4
#define DD 32
#define CC 47
#define NEG_SLOPE 0.2f

// ---------------- scratch (__device__ globals; no allocation) ----------------
__device__ float g_feat[NN * HH * CC];   // 100000*188 = 75.2MB (max layer width)
__device__ float g_out [NN * HH * CC];   // aggregated output / next-layer input
__device__ float g_el  [NN * HH];
__device__ float g_er  [NN * HH];
__device__ float g_m   [NN * HH];
__device__ float g_den [NN * HH];
__device__ float g_e   [EE * HH];        // e / ex per (edge, head), reused in place

// ---------------- helpers ----------------
__device__ __forceinline__ void atomicMaxF(float* addr, float v) {
    // init = -inf; positives compare correctly as signed ints,
    // negatives compare reverse-order as unsigned ints (uint-min == float-max)
    if (v >= 0.f) atomicMax((int*)addr, __float_as_int(v));
    else          atomicMin((unsigned int*)addr, __float_as_uint(v));
}

// ---------------- SGEMM: g_feat[M,N] = A[M,K] @ B[K,N] ----------------
// 64x64 tile, BK=16, 256 threads, 4x4 register tile per thread.
__global__ void sgemm_kernel(const float* __restrict__ A, const float* __restrict__ B,
                             int M, int N, int K) {
    __shared__ float As[16][64 + 1];
    __shared__ float Bs[16][64 + 1];
    const int tid = threadIdx.x;
    const int tx = tid & 15;
    const int ty = tid >> 4;
    const int row0 = blockIdx.x * 64;
    const int col0 = blockIdx.y * 64;

    float acc[4][4] = {};

    for (int k0 = 0; k0 < K; k0 += 16) {
        for (int i = tid; i < 64 * 16; i += 256) {
            int m = i >> 4, kk = i & 15;
            int gr = row0 + m;
            As[kk][m] = (gr < M) ? A[(long)gr * K + (k0 + kk)] : 0.f;
        }
        for (int i = tid; i < 16 * 64; i += 256) {
            int kk = i >> 6, n = i & 63;
            int gc = col0 + n;
            Bs[kk][n] = (gc < N) ? B[(long)(k0 + kk) * N + gc] : 0.f;
        }
        __syncthreads();
        #pragma unroll
        for (int kk = 0; kk < 16; kk++) {
            float a[4], b[4];
            #pragma unroll
            for (int i = 0; i < 4; i++) a[i] = As[kk][ty * 4 + i];
            #pragma unroll
            for (int j = 0; j < 4; j++) b[j] = Bs[kk][tx * 4 + j];
            #pragma unroll
            for (int i = 0; i < 4; i++)
                #pragma unroll
                for (int j = 0; j < 4; j++)
                    acc[i][j] += a[i] * b[j];
        }
        __syncthreads();
    }

    #pragma unroll
    for (int i = 0; i < 4; i++) {
        int gr = row0 + ty * 4 + i;
        if (gr >= M) continue;
        #pragma unroll
        for (int j = 0; j < 4; j++) {
            int gc = col0 + tx * 4 + j;
            if (gc < N) g_feat[(long)gr * N + gc] = acc[i][j];
        }
    }
}

// ---------------- el/er + init m/den: per (node, head) ----------------
__global__ void elr_init_kernel(const float* __restrict__ al, const float* __restrict__ ar,
                                int od) {
    int idx = blockIdx.x * blockDim.x + threadIdx.x;   // n*H + h
    if (idx >= NN * HH) return;
    int n = idx / HH, h = idx % HH;
    const float* f = g_feat + (long)n * HH * od + h * od;
    const float* alh = al + h * od;
    const float* arh = ar + h * od;
    float sl = 0.f, sr = 0.f;
    for (int d = 0; d < od; d++) { float v = f[d]; sl += v * alh[d]; sr += v * arh[d]; }
    g_el[idx] = sl;
    g_er[idx] = sr;
    g_m[idx] = -CUDART_INF_F;
    g_den[idx] = 0.f;
}

// ---------------- zero the aggregation output ----------------
__global__ void zero_kernel(int n) {
    int idx = blockIdx.x * blockDim.x + threadIdx.x;
    if (idx < n) g_out[idx] = 0.f;
}

// ---------------- edge pass A: e = leaky_relu(el[src]+er[dst]); seg-max ----------------
__global__ void edge_max_kernel(const int* __restrict__ src, const int* __restrict__ dst) {
    int idx = blockIdx.x * blockDim.x + threadIdx.x;   // e*H + h
    if (idx >= EE * HH) return;
    int e = idx / HH, h = idx % HH;
    int s = src[e], d = dst[e];
    float v = g_el[s * HH + h] + g_er[d * HH + h];
    v = (v > 0.f) ? v : NEG_SLOPE * v;
    g_e[idx] = v;
    atomicMaxF(&g_m[d * HH + h], v);
}

// ---------------- edge pass B: ex = exp(e - m[dst]); seg-sum into den ----------------
__global__ void edge_exp_kernel(const int* __restrict__ dst) {
    int idx = blockIdx.x * blockDim.x + threadIdx.x;
    if (idx >= EE * HH) return;
    int e = idx / HH, h = idx % HH;
    int d = dst[e];
    float ex = __expf(g_e[idx] - g_m[d * HH + h]);
    g_e[idx] = ex;
    atomicAdd(&g_den[d * HH + h], ex);
}

// ---------------- edge pass C: out[dst] += alpha * feat[src]  (warp per edge) ----------------
__global__ void aggregate_kernel(const int* __restrict__ src, const int* __restrict__ dst,
                                 int od) {
    int warp = (blockIdx.x * blockDim.x + threadIdx.x) >> 5;
    int lane = threadIdx.x & 31;
    if (warp >= EE) return;
    int s = src[warp], d = dst[warp];
    int F = HH * od;
    const float* fs = g_feat + (long)s * F;
    float* op = g_out + (long)d * F;
    // per-lane alpha: lane j covers features j, j+32, ... ; head = feature/od
    for (int j = lane; j < F; j += 32) {
        int h = j / od;
        float alpha = g_e[warp * HH + h] / g_den[d * HH + h];
        atomicAdd(&op[j], alpha * fs[j]);
    }
}

// ---------------- bias + relu epilogue ----------------
__global__ void bias_relu_kernel(const float* __restrict__ b, int F) {
    int idx = blockIdx.x * blockDim.x + threadIdx.x;
    if (idx >= NN * F) return;
    g_out[idx] = fmaxf(g_out[idx] + b[idx % F], 0.f);
}

// ---------------- final: head-mean (+bias) + log_softmax  (warp per node) ----------------
__global__ void final_kernel(const float* __restrict__ b3, float* __restrict__ y) {
    int node = (blockIdx.x * blockDim.x + threadIdx.x) >> 5;
    int lane = threadIdx.x & 31;
    if (node >= NN) return;
    const float* row = g_out + (long)node * HH * CC;

    float a0 = 0.f, a1 = 0.f;
    float v0 = -CUDART_INF_F, v1 = -CUDART_INF_F;
    if (lane < CC) {
        float sum = 0.f;
        #pragma unroll
        for (int h = 0; h < HH; h++) sum += row[h * CC + lane] + b3[h * CC + lane];
        a0 = sum * 0.25f; v0 = a0;
    }
    int c1 = lane + 32;
    if (c1 < CC) {
        float sum = 0.f;
        #pragma unroll
        for (int h = 0; h < HH; h++) sum += row[h * CC + c1] + b3[h * CC + c1];
        a1 = sum * 0.25f; v1 = a1;
    }
    float mx = fmaxf(v0, v1);
    #pragma unroll
    for (int o = 16; o > 0; o >>= 1) mx = fmaxf(mx, __shfl_xor_sync(0xffffffffu, mx, o));
    float s = 0.f;
    if (lane < CC) s += __expf(a0 - mx);
    if (c1 < CC)   s += __expf(a1 - mx);
    #pragma unroll
    for (int o = 16; o > 0; o >>= 1) s += __shfl_xor_sync(0xffffffffu, s, o);
    float lse = logf(s);
    if (lane < CC) y[(long)node * CC + lane] = a0 - mx - lse;
    if (c1 < CC)   y[(long)node * CC + c1] = a1 - mx - lse;
}

// ---------------- host-side layer driver (kernel launches only) ----------------
static void run_layer(const float* hin, int Fin,
                      const float* W, const float* al, const float* ar, const float* b,
                      int od, bool act,
                      const int* src, const int* dst) {
    const int F = HH * od;
    dim3 gg((NN + 63) / 64, (F + 63) / 64);
    sgemm_kernel<<<gg, 256>>>(hin, W, NN, F, Fin);
    elr_init_kernel<<<(NN * HH + 255) / 256, 256>>>(al, ar, od);
    zero_kernel<<<(NN * F + 255) / 256, 256>>>(NN * F);
    edge_max_kernel<<<(EE * HH + 255) / 256, 256>>>(src, dst);
    edge_exp_kernel<<<(EE * HH + 255) / 256, 256>>>(dst);
    aggregate_kernel<<<(EE + 7) / 8, 256>>>(src, dst, od);   // warp per edge
    if (act) bias_relu_kernel<<<(NN * F + 255) / 256, 256>>>(b, F);
}

// device-symbol address helper for the cross-layer input (g_out read by sgemm)
__global__ void noop_kernel() {}

extern "C" void kernel_launch(void* const* d_in, const int* in_sizes, int n_in,
                              void* d_out, int out_size) {
    const float* x   = (const float*)d_in[0];
    const int*   src = (const int*)  d_in[1];
    const int*   dst = (const int*)  d_in[2];
    const float* W1  = (const float*)d_in[3];
    const float* al1 = (const float*)d_in[4];
    const float* ar1 = (const float*)d_in[5];
    // b1 = d_in[6] (zeros; applied via bias_relu for exactness)
    const float* b1  = (const float*)d_in[6];
    const float* W2  = (const float*)d_in[7];
    const float* al2 = (const float*)d_in[8];
    const float* ar2 = (const float*)d_in[9];
    const float* b2  = (const float*)d_in[10];
    const float* W3  = (const float*)d_in[11];
    const float* al3 = (const float*)d_in[12];
    const float* ar3 = (const float*)d_in[13];
    const float* b3  = (const float*)d_in[14];
    float* y = (float*)d_out;

    // g_out device address, obtained once per process (static, outside capture path
    // concerns: cudaGetSymbolAddress is not a stream operation, but cache it anyway)
    static float* outb = nullptr;
    if (!outb) cudaGetSymbolAddress((void**)&outb, g_out);

    // layer 1: x [N,256] -> g_out [N,128], relu
    run_layer(x, F_IN, W1, al1, ar1, b1, DD, true, src, dst);
    // layer 2: g_out [N,128] -> g_out [N,128], relu
    run_layer(outb, HH * DD, W2, al2, ar2, b2, DD, true, src, dst);
    // layer 3: g_out [N,128] -> g_out [N,188], no activation (bias fused into final)
    run_layer(outb, HH * DD, W3, al3, ar3, b3, CC, false, src, dst);
    // head-mean + bias + log_softmax
    final_kernel<<<(NN + 7) / 8, 256>>>(b3, y);
}

// round 4
// speedup vs baseline: 2.6696x; 2.6696x over previous
#include <cuda_runtime.h>
#include <cuda_bf16.h>
#include <math_constants.h>

#define NN 100000
#define EE 1600000
#define F_IN 256
#define HH 4
#define DD 32
#define CC 47
#define NEG_SLOPE 0.2f

// ---------------- scratch (__device__ globals; no allocation) ----------------
__device__ float g_feat [NN * HH * CC];   // gemm output [N, H*od] (max 188 wide)
__device__ float g_out  [NN * HH * CC];   // aggregated output / next-layer input
__device__ float g_el   [NN * HH];        // [N,4] -> float4 per node
__device__ float g_er   [NN * HH];
__device__ float g_alpha[EE * HH];        // CSR-ordered e/ex/alpha per (pos, head)
__device__ int   g_deg  [NN];
__device__ int   g_cnt  [NN];
__device__ int   g_rowptr[NN + 1];
__device__ int   g_csrc [EE];             // src node per CSR position

// ====================== CSR build (once per launch) ======================
__global__ void __launch_bounds__(256)
zero_int_kernel(int* __restrict__ p, int n) {
    int i = blockIdx.x * blockDim.x + threadIdx.x;
    if (i < n) p[i] = 0;
}

__global__ void __launch_bounds__(256)
hist_kernel(const int* __restrict__ dst) {
    int e = blockIdx.x * blockDim.x + threadIdx.x;
    if (e < EE) atomicAdd(&g_deg[dst[e]], 1);
}

// single-block exclusive scan of g_deg -> g_rowptr
__global__ void __launch_bounds__(1024)
scan_kernel() {
    __shared__ int sh[1024];
    const int t = threadIdx.x;
    const int CH = (NN + 1023) / 1024;   // 98
    const int base = t * CH;
    int sum = 0;
    #pragma unroll 1
    for (int i = 0; i < CH; i++) {
        int idx = base + i;
        if (idx < NN) sum += g_deg[idx];
    }
    sh[t] = sum;
    __syncthreads();
    for (int o = 1; o < 1024; o <<= 1) {
        int v = (t >= o) ? sh[t - o] : 0;
        __syncthreads();
        sh[t] += v;
        __syncthreads();
    }
    int excl = (t == 0) ? 0 : sh[t - 1];
    #pragma unroll 1
    for (int i = 0; i < CH; i++) {
        int idx = base + i;
        if (idx < NN) { g_rowptr[idx] = excl; excl += g_deg[idx]; }
    }
    if (t == 1023) g_rowptr[NN] = sh[1023];
}

__global__ void __launch_bounds__(256)
scatter_kernel(const int* __restrict__ src, const int* __restrict__ dst) {
    int e = blockIdx.x * blockDim.x + threadIdx.x;
    if (e >= EE) return;
    int d = dst[e];
    int p = g_rowptr[d] + atomicAdd(&g_cnt[d], 1);
    g_csrc[p] = src[e];
}

// ====================== SGEMM: g_feat[M,N] = A[M,K] @ B[K,N] ======================
// 64x64 tile, BK=16, 256 threads, 4x4 register tile per thread.
__global__ void __launch_bounds__(256)
sgemm_kernel(const float* __restrict__ A, const float* __restrict__ B,
             int M, int N, int K) {
    __shared__ float As[16][64 + 1];
    __shared__ float Bs[16][64 + 1];
    const int tid = threadIdx.x;
    const int tx = tid & 15;
    const int ty = tid >> 4;
    const int row0 = blockIdx.x * 64;
    const int col0 = blockIdx.y * 64;

    float acc[4][4] = {};

    for (int k0 = 0; k0 < K; k0 += 16) {
        for (int i = tid; i < 64 * 16; i += 256) {
            int m = i >> 4, kk = i & 15;
            int gr = row0 + m;
            As[kk][m] = (gr < M) ? A[(long)gr * K + (k0 + kk)] : 0.f;
        }
        for (int i = tid; i < 16 * 64; i += 256) {
            int kk = i >> 6, n = i & 63;
            int gc = col0 + n;
            Bs[kk][n] = (gc < N) ? B[(long)(k0 + kk) * N + gc] : 0.f;
        }
        __syncthreads();
        #pragma unroll
        for (int kk = 0; kk < 16; kk++) {
            float a[4], b[4];
            #pragma unroll
            for (int i = 0; i < 4; i++) a[i] = As[kk][ty * 4 + i];
            #pragma unroll
            for (int j = 0; j < 4; j++) b[j] = Bs[kk][tx * 4 + j];
            #pragma unroll
            for (int i = 0; i < 4; i++)
                #pragma unroll
                for (int j = 0; j < 4; j++)
                    acc[i][j] += a[i] * b[j];
        }
        __syncthreads();
    }

    #pragma unroll
    for (int i = 0; i < 4; i++) {
        int gr = row0 + ty * 4 + i;
        if (gr >= M) continue;
        #pragma unroll
        for (int j = 0; j < 4; j++) {
            int gc = col0 + tx * 4 + j;
            if (gc < N) g_feat[(long)gr * N + gc] = acc[i][j];
        }
    }
}

// ====================== el/er per (node, head) ======================
__global__ void __launch_bounds__(256)
elr_kernel(const float* __restrict__ al, const float* __restrict__ ar, int od) {
    int idx = blockIdx.x * blockDim.x + threadIdx.x;   // n*H + h
    if (idx >= NN * HH) return;
    int n = idx >> 2, h = idx & 3;
    const float* f = g_feat + (long)n * HH * od + h * od;
    const float* alh = al + h * od;
    const float* arh = ar + h * od;
    float sl = 0.f, sr = 0.f;
    for (int d = 0; d < od; d++) { float v = f[d]; sl += v * alh[d]; sr += v * arh[d]; }
    g_el[idx] = sl;
    g_er[idx] = sr;
}

// ====================== fused per-node edge softmax (warp per node) ======================
__device__ __forceinline__ float lrelu(float v) { return v > 0.f ? v : NEG_SLOPE * v; }

__global__ void __launch_bounds__(256)
attn_softmax_kernel() {
    int node = (blockIdx.x * blockDim.x + threadIdx.x) >> 5;
    int lane = threadIdx.x & 31;
    if (node >= NN) return;
    int r0 = g_rowptr[node], r1 = g_rowptr[node + 1];

    float4 erd = *(const float4*)&g_er[node * 4];

    // pass 1: e = leaky(el[src] + er[node]); store; per-head max
    float mx0 = -CUDART_INF_F, mx1 = -CUDART_INF_F, mx2 = -CUDART_INF_F, mx3 = -CUDART_INF_F;
    for (int i = r0 + lane; i < r1; i += 32) {
        int s = g_csrc[i];
        float4 ev = *(const float4*)&g_el[s * 4];
        float4 e;
        e.x = lrelu(ev.x + erd.x);
        e.y = lrelu(ev.y + erd.y);
        e.z = lrelu(ev.z + erd.z);
        e.w = lrelu(ev.w + erd.w);
        *(float4*)&g_alpha[i * 4] = e;
        mx0 = fmaxf(mx0, e.x); mx1 = fmaxf(mx1, e.y);
        mx2 = fmaxf(mx2, e.z); mx3 = fmaxf(mx3, e.w);
    }
    #pragma unroll
    for (int o = 16; o > 0; o >>= 1) {
        mx0 = fmaxf(mx0, __shfl_xor_sync(0xffffffffu, mx0, o));
        mx1 = fmaxf(mx1, __shfl_xor_sync(0xffffffffu, mx1, o));
        mx2 = fmaxf(mx2, __shfl_xor_sync(0xffffffffu, mx2, o));
        mx3 = fmaxf(mx3, __shfl_xor_sync(0xffffffffu, mx3, o));
    }

    // pass 2: ex = exp(e - m); store; per-head sum
    float s0 = 0.f, s1 = 0.f, s2 = 0.f, s3 = 0.f;
    for (int i = r0 + lane; i < r1; i += 32) {
        float4 e = *(const float4*)&g_alpha[i * 4];
        e.x = __expf(e.x - mx0);
        e.y = __expf(e.y - mx1);
        e.z = __expf(e.z - mx2);
        e.w = __expf(e.w - mx3);
        *(float4*)&g_alpha[i * 4] = e;
        s0 += e.x; s1 += e.y; s2 += e.z; s3 += e.w;
    }
    #pragma unroll
    for (int o = 16; o > 0; o >>= 1) {
        s0 += __shfl_xor_sync(0xffffffffu, s0, o);
        s1 += __shfl_xor_sync(0xffffffffu, s1, o);
        s2 += __shfl_xor_sync(0xffffffffu, s2, o);
        s3 += __shfl_xor_sync(0xffffffffu, s3, o);
    }
    float i0 = 1.f / s0, i1 = 1.f / s1, i2 = 1.f / s2, i3 = 1.f / s3;

    // pass 3: alpha = ex / den
    for (int i = r0 + lane; i < r1; i += 32) {
        float4 e = *(const float4*)&g_alpha[i * 4];
        e.x *= i0; e.y *= i1; e.z *= i2; e.w *= i3;
        *(float4*)&g_alpha[i * 4] = e;
    }
}

// ====================== aggregation F=128 (warp per node, atomic-free) ======================
// lane owns features [lane*4, lane*4+4); head = lane>>3. bias+relu fused.
__global__ void __launch_bounds__(256)
agg128_kernel(const float* __restrict__ bias) {
    int node = (blockIdx.x * blockDim.x + threadIdx.x) >> 5;
    int lane = threadIdx.x & 31;
    if (node >= NN) return;
    int r0 = g_rowptr[node], r1 = g_rowptr[node + 1];
    const int head = lane >> 3;

    float4 acc = {0.f, 0.f, 0.f, 0.f};
    int i = r0;
    for (; i + 1 < r1; i += 2) {
        int sA = g_csrc[i], sB = g_csrc[i + 1];
        float aA = g_alpha[i * 4 + head];
        float aB = g_alpha[(i + 1) * 4 + head];
        float4 fA = *(const float4*)&g_feat[(long)sA * 128 + lane * 4];
        float4 fB = *(const float4*)&g_feat[(long)sB * 128 + lane * 4];
        acc.x += aA * fA.x + aB * fB.x;
        acc.y += aA * fA.y + aB * fB.y;
        acc.z += aA * fA.z + aB * fB.z;
        acc.w += aA * fA.w + aB * fB.w;
    }
    if (i < r1) {
        int s = g_csrc[i];
        float a = g_alpha[i * 4 + head];
        float4 f = *(const float4*)&g_feat[(long)s * 128 + lane * 4];
        acc.x += a * f.x; acc.y += a * f.y; acc.z += a * f.z; acc.w += a * f.w;
    }
    float4 b = *(const float4*)&bias[lane * 4];
    acc.x = fmaxf(acc.x + b.x, 0.f);
    acc.y = fmaxf(acc.y + b.y, 0.f);
    acc.z = fmaxf(acc.z + b.z, 0.f);
    acc.w = fmaxf(acc.w + b.w, 0.f);
    *(float4*)&g_out[(long)node * 128 + lane * 4] = acc;
}

// ====================== aggregation F=188 (warp per node; no bias/act) ======================
__global__ void __launch_bounds__(256)
agg188_kernel() {
    int node = (blockIdx.x * blockDim.x + threadIdx.x) >> 5;
    int lane = threadIdx.x & 31;
    if (node >= NN) return;
    int r0 = g_rowptr[node], r1 = g_rowptr[node + 1];

    float acc[6] = {0.f, 0.f, 0.f, 0.f, 0.f, 0.f};
    int headk[6];
    #pragma unroll
    for (int k = 0; k < 6; k++) headk[k] = (lane + 32 * k) / CC;  // feature/47

    for (int i = r0; i < r1; i++) {
        int s = g_csrc[i];
        const float* fs = g_feat + (long)s * 188;
        const float* ap = g_alpha + (long)i * 4;
        #pragma unroll
        for (int k = 0; k < 6; k++) {
            int j = lane + 32 * k;
            if (j < 188) acc[k] += ap[headk[k]] * fs[j];
        }
    }
    float* op = g_out + (long)node * 188;
    #pragma unroll
    for (int k = 0; k < 6; k++) {
        int j = lane + 32 * k;
        if (j < 188) op[j] = acc[k];
    }
}

// ====================== final: head-mean (+bias) + log_softmax (warp per node) ======================
__global__ void __launch_bounds__(256)
final_kernel(const float* __restrict__ b3, float* __restrict__ y) {
    int node = (blockIdx.x * blockDim.x + threadIdx.x) >> 5;
    int lane = threadIdx.x & 31;
    if (node >= NN) return;
    const float* row = g_out + (long)node * HH * CC;

    float a0 = 0.f, a1 = 0.f;
    float v0 = -CUDART_INF_F, v1 = -CUDART_INF_F;
    if (lane < CC) {
        float sum = 0.f;
        #pragma unroll
        for (int h = 0; h < HH; h++) sum += row[h * CC + lane] + b3[h * CC + lane];
        a0 = sum * 0.25f; v0 = a0;
    }
    int c1 = lane + 32;
    if (c1 < CC) {
        float sum = 0.f;
        #pragma unroll
        for (int h = 0; h < HH; h++) sum += row[h * CC + c1] + b3[h * CC + c1];
        a1 = sum * 0.25f; v1 = a1;
    }
    float mx = fmaxf(v0, v1);
    #pragma unroll
    for (int o = 16; o > 0; o >>= 1) mx = fmaxf(mx, __shfl_xor_sync(0xffffffffu, mx, o));
    float s = 0.f;
    if (lane < CC) s += __expf(a0 - mx);
    if (c1 < CC)   s += __expf(a1 - mx);
    #pragma unroll
    for (int o = 16; o > 0; o >>= 1) s += __shfl_xor_sync(0xffffffffu, s, o);
    float lse = logf(s);
    if (lane < CC) y[(long)node * CC + lane] = a0 - mx - lse;
    if (c1 < CC)   y[(long)node * CC + c1] = a1 - mx - lse;
}

// ====================== host driver ======================
extern "C" void kernel_launch(void* const* d_in, const int* in_sizes, int n_in,
                              void* d_out, int out_size) {
    const float* x   = (const float*)d_in[0];
    const int*   src = (const int*)  d_in[1];
    const int*   dst = (const int*)  d_in[2];
    const float* W1  = (const float*)d_in[3];
    const float* al1 = (const float*)d_in[4];
    const float* ar1 = (const float*)d_in[5];
    const float* b1  = (const float*)d_in[6];
    const float* W2  = (const float*)d_in[7];
    const float* al2 = (const float*)d_in[8];
    const float* ar2 = (const float*)d_in[9];
    const float* b2  = (const float*)d_in[10];
    const float* W3  = (const float*)d_in[11];
    const float* al3 = (const float*)d_in[12];
    const float* ar3 = (const float*)d_in[13];
    const float* b3  = (const float*)d_in[14];
    float* y = (float*)d_out;

    static float* outb = nullptr;
    static int* degp = nullptr;
    static int* cntp = nullptr;
    if (!outb) {
        cudaGetSymbolAddress((void**)&outb, g_out);
        cudaGetSymbolAddress((void**)&degp, g_deg);
        cudaGetSymbolAddress((void**)&cntp, g_cnt);
    }

    const int TB = 256;
    const int nodeWarpGrid = (NN + 7) / 8;   // 8 warps per 256-thread block

    // ---- CSR build (graph static across layers) ----
    zero_int_kernel<<<(NN + TB - 1) / TB, TB>>>(degp, NN);
    hist_kernel<<<(EE + TB - 1) / TB, TB>>>(dst);
    scan_kernel<<<1, 1024>>>();
    zero_int_kernel<<<(NN + TB - 1) / TB, TB>>>(cntp, NN);
    scatter_kernel<<<(EE + TB - 1) / TB, TB>>>(src, dst);

    // ---- layer 1: x [N,256] -> g_out [N,128] ----
    {
        dim3 gg((NN + 63) / 64, (128 + 63) / 64);
        sgemm_kernel<<<gg, TB>>>(x, W1, NN, 128, F_IN);
        elr_kernel<<<(NN * HH + TB - 1) / TB, TB>>>(al1, ar1, DD);
        attn_softmax_kernel<<<nodeWarpGrid, TB>>>();
        agg128_kernel<<<nodeWarpGrid, TB>>>(b1);
    }
    // ---- layer 2: g_out [N,128] -> g_out [N,128] ----
    {
        dim3 gg((NN + 63) / 64, (128 + 63) / 64);
        sgemm_kernel<<<gg, TB>>>(outb, W2, NN, 128, 128);
        elr_kernel<<<(NN * HH + TB - 1) / TB, TB>>>(al2, ar2, DD);
        attn_softmax_kernel<<<nodeWarpGrid, TB>>>();
        agg128_kernel<<<nodeWarpGrid, TB>>>(b2);
    }
    // ---- layer 3: g_out [N,128] -> g_out [N,188] (bias fused into final) ----
    {
        dim3 gg((NN + 63) / 64, (188 + 63) / 64);
        sgemm_kernel<<<gg, TB>>>(outb, W3, NN, 188, 128);
        elr_kernel<<<(NN * HH + TB - 1) / TB, TB>>>(al3, ar3, CC);
        attn_softmax_kernel<<<nodeWarpGrid, TB>>>();
        agg188_kernel<<<nodeWarpGrid, TB>>>();
    }
    // ---- head-mean + bias + log_softmax ----
    final_kernel<<<(NN + 7) / 8, TB>>>(b3, y);
}

// round 5
// speedup vs baseline: 3.2684x; 1.2243x over previous
#include <cuda_runtime.h>
#include <cuda_bf16.h>
#include <math_constants.h>

#define NN 100000
#define EE 1600000
#define F_IN 256
#define HH 4
#define DD 32
#define CC 47
#define NEG_SLOPE 0.2f

#define BM 128
#define BN 128
#define BK 16

// ---------------- scratch (__device__ globals; no allocation) ----------------
__device__ float g_feat [NN * HH * CC];   // gemm output [N, H*od] (max 188 wide)
__device__ float g_out  [NN * HH * CC];   // aggregated output / next-layer input
__device__ float g_el   [NN * HH];        // [N,4] -> float4 per node
__device__ float g_er   [NN * HH];
__device__ float g_inv  [NN * HH];        // 1/den per (node, head)
__device__ float g_alpha[EE * HH];        // CSR-ordered e/ex per (pos, head)
__device__ int   g_deg  [NN];
__device__ int   g_cnt  [NN];
__device__ int   g_rowptr[NN + 1];
__device__ int   g_csrc [EE];             // src node per CSR position

// ====================== CSR build (once per launch) ======================
__global__ void __launch_bounds__(256)
zero2_kernel() {
    int i = blockIdx.x * blockDim.x + threadIdx.x;
    if (i < NN) { g_deg[i] = 0; g_cnt[i] = 0; }
}

__global__ void __launch_bounds__(256)
hist_kernel(const int* __restrict__ dst) {
    int e = blockIdx.x * blockDim.x + threadIdx.x;
    if (e < EE) atomicAdd(&g_deg[dst[e]], 1);
}

// single-block exclusive scan of g_deg -> g_rowptr
__global__ void __launch_bounds__(1024)
scan_kernel() {
    __shared__ int sh[1024];
    const int t = threadIdx.x;
    const int CH = (NN + 1023) / 1024;   // 98
    const int base = t * CH;
    int sum = 0;
    #pragma unroll 1
    for (int i = 0; i < CH; i++) {
        int idx = base + i;
        if (idx < NN) sum += g_deg[idx];
    }
    sh[t] = sum;
    __syncthreads();
    for (int o = 1; o < 1024; o <<= 1) {
        int v = (t >= o) ? sh[t - o] : 0;
        __syncthreads();
        sh[t] += v;
        __syncthreads();
    }
    int excl = (t == 0) ? 0 : sh[t - 1];
    #pragma unroll 1
    for (int i = 0; i < CH; i++) {
        int idx = base + i;
        if (idx < NN) { g_rowptr[idx] = excl; excl += g_deg[idx]; }
    }
    if (t == 1023) g_rowptr[NN] = sh[1023];
}

__global__ void __launch_bounds__(256)
scatter_kernel(const int* __restrict__ src, const int* __restrict__ dst) {
    int e = blockIdx.x * blockDim.x + threadIdx.x;
    if (e >= EE) return;
    int d = dst[e];
    int p = g_rowptr[d] + atomicAdd(&g_cnt[d], 1);
    g_csrc[p] = src[e];
}

// ====================== SGEMM: g_feat[M,N] = A[M,K] @ B[K,N] ======================
// 128x128 tile, BK=16, 256 threads, 8x8 per thread, double-buffered,
// packed fp32x2 FMAs (FFMA2) via PTX.
__device__ __forceinline__ void load_tile(
    const float* __restrict__ A, const float* __restrict__ B,
    int M, int N, int K, int row0, int col0, int k0, int tid,
    float (* __restrict__ As)[BM + 2], float (* __restrict__ Bs)[BN]) {
    #pragma unroll
    for (int t = 0; t < 2; t++) {
        int fi = tid + t * 256;
        {   // A tile: 128 rows x 16 k, transposed into As[k][m]
            int row = fi >> 2, kq = fi & 3;
            int gr = row0 + row;
            float4 v = make_float4(0.f, 0.f, 0.f, 0.f);
            if (gr < M) v = *(const float4*)&A[(long)gr * K + k0 + kq * 4];
            As[kq * 4 + 0][row] = v.x;
            As[kq * 4 + 1][row] = v.y;
            As[kq * 4 + 2][row] = v.z;
            As[kq * 4 + 3][row] = v.w;
        }
        {   // B tile: 16 k x 128 n
            int krow = fi >> 5, nq = fi & 31;
            int gc = col0 + nq * 4;
            float4 v = make_float4(0.f, 0.f, 0.f, 0.f);
            if (gc < N) v = *(const float4*)&B[(long)(k0 + krow) * N + gc];
            *(float4*)&Bs[krow][nq * 4] = v;
        }
    }
}

__global__ void __launch_bounds__(256)
sgemm_kernel(const float* __restrict__ A, const float* __restrict__ B,
             int M, int N, int K) {
    __shared__ __align__(16) float As[2][BK][BM + 2];
    __shared__ __align__(16) float Bs[2][BK][BN];
    const int tid = threadIdx.x;
    const int tx = tid & 15;          // col group: cols tx*8 .. +8
    const int ty = tid >> 4;          // row group: rows ty*8 .. +8
    const int row0 = blockIdx.x * BM;
    const int col0 = blockIdx.y * BN;

    // acc[r][j] packs rows (ty*8+2r, ty*8+2r+1) for col tx*8+j as f32x2
    unsigned long long acc[4][8];
    #pragma unroll
    for (int r = 0; r < 4; r++)
        #pragma unroll
        for (int j = 0; j < 8; j++) acc[r][j] = 0ull;

    load_tile(A, B, M, N, K, row0, col0, 0, tid, As[0], Bs[0]);
    __syncthreads();

    int buf = 0;
    for (int k0 = 0; k0 < K; k0 += BK) {
        if (k0 + BK < K)
            load_tile(A, B, M, N, K, row0, col0, k0 + BK, tid, As[buf ^ 1], Bs[buf ^ 1]);
        #pragma unroll
        for (int kk = 0; kk < BK; kk++) {
            unsigned long long ap[4];
            #pragma unroll
            for (int r = 0; r < 4; r++)
                ap[r] = *(const unsigned long long*)&As[buf][kk][ty * 8 + r * 2];
            float4 b0 = *(const float4*)&Bs[buf][kk][tx * 8];
            float4 b1 = *(const float4*)&Bs[buf][kk][tx * 8 + 4];
            float bj[8] = {b0.x, b0.y, b0.z, b0.w, b1.x, b1.y, b1.z, b1.w};
            unsigned long long bd[8];
            #pragma unroll
            for (int j = 0; j < 8; j++)
                asm("mov.b64 %0, {%1, %1};" : "=l"(bd[j]) : "f"(bj[j]));
            #pragma unroll
            for (int r = 0; r < 4; r++)
                #pragma unroll
                for (int j = 0; j < 8; j++)
                    asm("fma.rn.f32x2 %0, %1, %2, %0;"
                        : "+l"(acc[r][j]) : "l"(ap[r]), "l"(bd[j]));
        }
        __syncthreads();
        buf ^= 1;
    }

    const int cbase = col0 + tx * 8;
    #pragma unroll
    for (int r = 0; r < 4; r++) {
        float lo[8], hi[8];
        #pragma unroll
        for (int j = 0; j < 8; j++)
            asm("mov.b64 {%0, %1}, %2;" : "=f"(lo[j]), "=f"(hi[j]) : "l"(acc[r][j]));
        int gr0 = row0 + ty * 8 + 2 * r;       // rows gr0, gr0+1
        #pragma unroll
        for (int p = 0; p < 2; p++) {
            int gr = gr0 + p;
            if (gr >= M) continue;
            const float* c = p ? hi : lo;
            if (cbase + 7 < N) {
                *(float4*)&g_feat[(long)gr * N + cbase]     = make_float4(c[0], c[1], c[2], c[3]);
                *(float4*)&g_feat[(long)gr * N + cbase + 4] = make_float4(c[4], c[5], c[6], c[7]);
            } else {
                for (int jj = 0; jj < 8; jj++)
                    if (cbase + jj < N) g_feat[(long)gr * N + cbase + jj] = c[jj];
            }
        }
    }
}

// ====================== el/er per (node, head) ======================
__global__ void __launch_bounds__(256)
elr_kernel(const float* __restrict__ al, const float* __restrict__ ar, int od) {
    int idx = blockIdx.x * blockDim.x + threadIdx.x;   // n*H + h
    if (idx >= NN * HH) return;
    int n = idx >> 2, h = idx & 3;
    const float* f = g_feat + (long)n * HH * od + h * od;
    const float* alh = al + h * od;
    const float* arh = ar + h * od;
    float sl = 0.f, sr = 0.f;
    for (int d = 0; d < od; d++) { float v = f[d]; sl += v * alh[d]; sr += v * arh[d]; }
    g_el[idx] = sl;
    g_er[idx] = sr;
}

// ====================== fused per-node edge softmax (warp per node) ======================
// Writes ex into g_alpha and 1/den into g_inv (no pass-3 rescale).
__device__ __forceinline__ float lrelu(float v) { return v > 0.f ? v : NEG_SLOPE * v; }

__global__ void __launch_bounds__(256)
attn_softmax_kernel() {
    int node = (blockIdx.x * blockDim.x + threadIdx.x) >> 5;
    int lane = threadIdx.x & 31;
    if (node >= NN) return;
    int r0 = g_rowptr[node], r1 = g_rowptr[node + 1];

    float4 erd = *(const float4*)&g_er[node * 4];

    // pass 1: e = leaky(el[src] + er[node]); store; per-head max
    float mx0 = -CUDART_INF_F, mx1 = -CUDART_INF_F, mx2 = -CUDART_INF_F, mx3 = -CUDART_INF_F;
    for (int i = r0 + lane; i < r1; i += 32) {
        int s = g_csrc[i];
        float4 ev = *(const float4*)&g_el[s * 4];
        float4 e;
        e.x = lrelu(ev.x + erd.x);
        e.y = lrelu(ev.y + erd.y);
        e.z = lrelu(ev.z + erd.z);
        e.w = lrelu(ev.w + erd.w);
        *(float4*)&g_alpha[i * 4] = e;
        mx0 = fmaxf(mx0, e.x); mx1 = fmaxf(mx1, e.y);
        mx2 = fmaxf(mx2, e.z); mx3 = fmaxf(mx3, e.w);
    }
    #pragma unroll
    for (int o = 16; o > 0; o >>= 1) {
        mx0 = fmaxf(mx0, __shfl_xor_sync(0xffffffffu, mx0, o));
        mx1 = fmaxf(mx1, __shfl_xor_sync(0xffffffffu, mx1, o));
        mx2 = fmaxf(mx2, __shfl_xor_sync(0xffffffffu, mx2, o));
        mx3 = fmaxf(mx3, __shfl_xor_sync(0xffffffffu, mx3, o));
    }

    // pass 2: ex = exp(e - m); store; per-head sum
    float s0 = 0.f, s1 = 0.f, s2 = 0.f, s3 = 0.f;
    for (int i = r0 + lane; i < r1; i += 32) {
        float4 e = *(const float4*)&g_alpha[i * 4];
        e.x = __expf(e.x - mx0);
        e.y = __expf(e.y - mx1);
        e.z = __expf(e.z - mx2);
        e.w = __expf(e.w - mx3);
        *(float4*)&g_alpha[i * 4] = e;
        s0 += e.x; s1 += e.y; s2 += e.z; s3 += e.w;
    }
    #pragma unroll
    for (int o = 16; o > 0; o >>= 1) {
        s0 += __shfl_xor_sync(0xffffffffu, s0, o);
        s1 += __shfl_xor_sync(0xffffffffu, s1, o);
        s2 += __shfl_xor_sync(0xffffffffu, s2, o);
        s3 += __shfl_xor_sync(0xffffffffu, s3, o);
    }
    if (lane == 0)
        *(float4*)&g_inv[node * 4] = make_float4(1.f / s0, 1.f / s1, 1.f / s2, 1.f / s3);
}

// ====================== aggregation F=128 (warp per node, atomic-free) ======================
// lane owns features [lane*4, lane*4+4); head = lane>>3. bias+relu fused.
__global__ void __launch_bounds__(256)
agg128_kernel(const float* __restrict__ bias) {
    int node = (blockIdx.x * blockDim.x + threadIdx.x) >> 5;
    int lane = threadIdx.x & 31;
    if (node >= NN) return;
    int r0 = g_rowptr[node], r1 = g_rowptr[node + 1];
    const int head = lane >> 3;

    float4 inv4 = *(const float4*)&g_inv[node * 4];
    float invh = (head < 2) ? (head == 0 ? inv4.x : inv4.y)
                            : (head == 2 ? inv4.z : inv4.w);

    float4 acc = {0.f, 0.f, 0.f, 0.f};
    int i = r0;
    for (; i + 3 < r1; i += 4) {
        int s0 = g_csrc[i],     s1 = g_csrc[i + 1];
        int s2 = g_csrc[i + 2], s3 = g_csrc[i + 3];
        float a0 = g_alpha[(i    ) * 4 + head] * invh;
        float a1 = g_alpha[(i + 1) * 4 + head] * invh;
        float a2 = g_alpha[(i + 2) * 4 + head] * invh;
        float a3 = g_alpha[(i + 3) * 4 + head] * invh;
        float4 f0 = *(const float4*)&g_feat[(long)s0 * 128 + lane * 4];
        float4 f1 = *(const float4*)&g_feat[(long)s1 * 128 + lane * 4];
        float4 f2 = *(const float4*)&g_feat[(long)s2 * 128 + lane * 4];
        float4 f3 = *(const float4*)&g_feat[(long)s3 * 128 + lane * 4];
        acc.x += a0 * f0.x + a1 * f1.x + a2 * f2.x + a3 * f3.x;
        acc.y += a0 * f0.y + a1 * f1.y + a2 * f2.y + a3 * f3.y;
        acc.z += a0 * f0.z + a1 * f1.z + a2 * f2.z + a3 * f3.z;
        acc.w += a0 * f0.w + a1 * f1.w + a2 * f2.w + a3 * f3.w;
    }
    for (; i < r1; i++) {
        int s = g_csrc[i];
        float a = g_alpha[i * 4 + head] * invh;
        float4 f = *(const float4*)&g_feat[(long)s * 128 + lane * 4];
        acc.x += a * f.x; acc.y += a * f.y; acc.z += a * f.z; acc.w += a * f.w;
    }
    float4 b = *(const float4*)&bias[lane * 4];
    acc.x = fmaxf(acc.x + b.x, 0.f);
    acc.y = fmaxf(acc.y + b.y, 0.f);
    acc.z = fmaxf(acc.z + b.z, 0.f);
    acc.w = fmaxf(acc.w + b.w, 0.f);
    *(float4*)&g_out[(long)node * 128 + lane * 4] = acc;
}

// ====================== aggregation F=188 (warp per node; no bias/act) ======================
__global__ void __launch_bounds__(256)
agg188_kernel() {
    int node = (blockIdx.x * blockDim.x + threadIdx.x) >> 5;
    int lane = threadIdx.x & 31;
    if (node >= NN) return;
    int r0 = g_rowptr[node], r1 = g_rowptr[node + 1];

    float4 inv4 = *(const float4*)&g_inv[node * 4];
    const float invarr[4] = {inv4.x, inv4.y, inv4.z, inv4.w};

    float acc[6] = {0.f, 0.f, 0.f, 0.f, 0.f, 0.f};
    int headk[6];
    float invk[6];
    #pragma unroll
    for (int k = 0; k < 6; k++) {
        headk[k] = (lane + 32 * k) / CC;  // feature/47
        invk[k] = invarr[headk[k]];
    }

    for (int i = r0; i < r1; i++) {
        int s = g_csrc[i];
        const float* fs = g_feat + (long)s * 188;
        const float* ap = g_alpha + (long)i * 4;
        #pragma unroll
        for (int k = 0; k < 6; k++) {
            int j = lane + 32 * k;
            if (j < 188) acc[k] += ap[headk[k]] * invk[k] * fs[j];
        }
    }
    float* op = g_out + (long)node * 188;
    #pragma unroll
    for (int k = 0; k < 6; k++) {
        int j = lane + 32 * k;
        if (j < 188) op[j] = acc[k];
    }
}

// ====================== final: head-mean (+bias) + log_softmax (warp per node) ======================
__global__ void __launch_bounds__(256)
final_kernel(const float* __restrict__ b3, float* __restrict__ y) {
    int node = (blockIdx.x * blockDim.x + threadIdx.x) >> 5;
    int lane = threadIdx.x & 31;
    if (node >= NN) return;
    const float* row = g_out + (long)node * HH * CC;

    float a0 = 0.f, a1 = 0.f;
    float v0 = -CUDART_INF_F, v1 = -CUDART_INF_F;
    if (lane < CC) {
        float sum = 0.f;
        #pragma unroll
        for (int h = 0; h < HH; h++) sum += row[h * CC + lane] + b3[h * CC + lane];
        a0 = sum * 0.25f; v0 = a0;
    }
    int c1 = lane + 32;
    if (c1 < CC) {
        float sum = 0.f;
        #pragma unroll
        for (int h = 0; h < HH; h++) sum += row[h * CC + c1] + b3[h * CC + c1];
        a1 = sum * 0.25f; v1 = a1;
    }
    float mx = fmaxf(v0, v1);
    #pragma unroll
    for (int o = 16; o > 0; o >>= 1) mx = fmaxf(mx, __shfl_xor_sync(0xffffffffu, mx, o));
    float s = 0.f;
    if (lane < CC) s += __expf(a0 - mx);
    if (c1 < CC)   s += __expf(a1 - mx);
    #pragma unroll
    for (int o = 16; o > 0; o >>= 1) s += __shfl_xor_sync(0xffffffffu, s, o);
    float lse = logf(s);
    if (lane < CC) y[(long)node * CC + lane] = a0 - mx - lse;
    if (c1 < CC)   y[(long)node * CC + c1] = a1 - mx - lse;
}

// ====================== host driver ======================
extern "C" void kernel_launch(void* const* d_in, const int* in_sizes, int n_in,
                              void* d_out, int out_size) {
    const float* x   = (const float*)d_in[0];
    const int*   src = (const int*)  d_in[1];
    const int*   dst = (const int*)  d_in[2];
    const float* W1  = (const float*)d_in[3];
    const float* al1 = (const float*)d_in[4];
    const float* ar1 = (const float*)d_in[5];
    const float* b1  = (const float*)d_in[6];
    const float* W2  = (const float*)d_in[7];
    const float* al2 = (const float*)d_in[8];
    const float* ar2 = (const float*)d_in[9];
    const float* b2  = (const float*)d_in[10];
    const float* W3  = (const float*)d_in[11];
    const float* al3 = (const float*)d_in[12];
    const float* ar3 = (const float*)d_in[13];
    const float* b3  = (const float*)d_in[14];
    float* y = (float*)d_out;

    static float* outb = nullptr;
    if (!outb) cudaGetSymbolAddress((void**)&outb, g_out);

    const int TB = 256;
    const int nodeWarpGrid = (NN + 7) / 8;   // 8 warps per 256-thread block

    // ---- CSR build (graph static across layers) ----
    zero2_kernel<<<(NN + TB - 1) / TB, TB>>>();
    hist_kernel<<<(EE + TB - 1) / TB, TB>>>(dst);
    scan_kernel<<<1, 1024>>>();
    scatter_kernel<<<(EE + TB - 1) / TB, TB>>>(src, dst);

    // ---- layer 1: x [N,256] -> g_out [N,128] ----
    {
        dim3 gg((NN + BM - 1) / BM, (128 + BN - 1) / BN);
        sgemm_kernel<<<gg, TB>>>(x, W1, NN, 128, F_IN);
        elr_kernel<<<(NN * HH + TB - 1) / TB, TB>>>(al1, ar1, DD);
        attn_softmax_kernel<<<nodeWarpGrid, TB>>>();
        agg128_kernel<<<nodeWarpGrid, TB>>>(b1);
    }
    // ---- layer 2: g_out [N,128] -> g_out [N,128] ----
    {
        dim3 gg((NN + BM - 1) / BM, (128 + BN - 1) / BN);
        sgemm_kernel<<<gg, TB>>>(outb, W2, NN, 128, 128);
        elr_kernel<<<(NN * HH + TB - 1) / TB, TB>>>(al2, ar2, DD);
        attn_softmax_kernel<<<nodeWarpGrid, TB>>>();
        agg128_kernel<<<nodeWarpGrid, TB>>>(b2);
    }
    // ---- layer 3: g_out [N,128] -> g_out [N,188] (bias fused into final) ----
    {
        dim3 gg((NN + BM - 1) / BM, (188 + BN - 1) / BN);
        sgemm_kernel<<<gg, TB>>>(outb, W3, NN, 188, 128);
        elr_kernel<<<(NN * HH + TB - 1) / TB, TB>>>(al3, ar3, CC);
        attn_softmax_kernel<<<nodeWarpGrid, TB>>>();
        agg188_kernel<<<nodeWarpGrid, TB>>>();
    }
    // ---- head-mean + bias + log_softmax ----
    final_kernel<<<(NN + 7) / 8, TB>>>(b3, y);
}